// round 14
// baseline (speedup 1.0000x reference)
#include <cuda_runtime.h>
#include <cuda_bf16.h>
#include <cstdint>

#define H1_ELEMS (64*128*64*64)
#define H2_ELEMS (64*256*32*32)
#define Z_ELEMS  (64*64*32*32)
#define D_ELEMS  (64*256*32*32)
#define D1_ELEMS (64*128*64*64)
#define RECON_ELEMS (64*3*128*128)
#define VQ_DIM 64
#define NCODE 512

__device__ float g_h1[H1_ELEMS];                 // NHWC fp32
__device__ __nv_bfloat16 g_h1hi[H1_ELEMS];
__device__ __nv_bfloat16 g_h1lo[H1_ELEMS];
__device__ float g_h2[H2_ELEMS];
__device__ float g_z[Z_ELEMS];
__device__ __nv_bfloat16 g_dhi[D_ELEMS];
__device__ __nv_bfloat16 g_dlo[D_ELEMS];
__device__ float g_d1[D1_ELEMS];
__device__ __nv_bfloat16 g_w2chi[256*1152];
__device__ __nv_bfloat16 g_w2clo[256*1152];
__device__ __nv_bfloat16 g_wd1hi[128*2304];
__device__ __nv_bfloat16 g_wd1lo[128*2304];
__device__ __nv_bfloat16 g_tabhi[NCODE*256];
__device__ __nv_bfloat16 g_tablo[NCODE*256];
__device__ float g_psum[128*2048];
__device__ float g_psq[128*2048];
__device__ float g_scale[128];
__device__ float g_shift[128];
__device__ float g_losspart[256];

typedef unsigned long long u64;
__device__ __forceinline__ u64 pack2(float a, float b) {
    u64 r; asm("mov.b64 %0, {%1,%2};" : "=l"(r) : "f"(a), "f"(b)); return r;
}
__device__ __forceinline__ u64 fma2(u64 a, u64 b, u64 c) {
    u64 d; asm("fma.rn.f32x2 %0, %1, %2, %3;" : "=l"(d) : "l"(a), "l"(b), "l"(c)); return d;
}
__device__ __forceinline__ u64 add2(u64 a, u64 b) {
    u64 d; asm("add.rn.f32x2 %0, %1, %2;" : "=l"(d) : "l"(a), "l"(b)); return d;
}
__device__ __forceinline__ float2 unpack2(u64 a) {
    float lo, hi; asm("mov.b64 {%0,%1}, %2;" : "=f"(lo), "=f"(hi) : "l"(a));
    return make_float2(lo, hi);
}
__device__ __forceinline__ void cp16(uint32_t saddr, const void* gaddr) {
    asm volatile("cp.async.cg.shared.global [%0], [%1], 16;" :: "r"(saddr), "l"(gaddr));
}
__device__ __forceinline__ void cp16z(uint32_t saddr, const void* gaddr, bool ok) {
    int sz = ok ? 16 : 0;
    asm volatile("cp.async.cg.shared.global [%0], [%1], 16, %2;" :: "r"(saddr), "l"(gaddr), "r"(sz));
}
#define CP_COMMIT() asm volatile("cp.async.commit_group;")
#define CP_WAIT(n)  asm volatile("cp.async.wait_group %0;" :: "n"(n))

#define SWZ(o) ((o) ^ ((((uint32_t)(o)) >> 3) & 0x70))

__device__ __forceinline__ void ldsm4(uint32_t* r, uint32_t addr) {
    asm volatile("ldmatrix.sync.aligned.m8n8.x4.shared.b16 {%0,%1,%2,%3}, [%4];"
                 : "=r"(r[0]), "=r"(r[1]), "=r"(r[2]), "=r"(r[3]) : "r"(addr));
}
__device__ __forceinline__ void mma16816(float* c, const uint32_t* a, const uint32_t* b) {
    asm volatile(
        "mma.sync.aligned.m16n8k16.row.col.f32.bf16.bf16.f32 "
        "{%0,%1,%2,%3}, {%4,%5,%6,%7}, {%8,%9}, {%0,%1,%2,%3};"
        : "+f"(c[0]), "+f"(c[1]), "+f"(c[2]), "+f"(c[3])
        : "r"(a[0]), "r"(a[1]), "r"(a[2]), "r"(a[3]), "r"(b[0]), "r"(b[1]));
}

// ---------------- weight prep ----------------
__global__ void wtrans_conv2_bf16(const float* __restrict__ w,
                                  __nv_bfloat16* __restrict__ whi, __nv_bfloat16* __restrict__ wlo)
{
    int i = blockIdx.x * 256 + threadIdx.x;
    if (i >= 256*1152) return;
    int co = i / 1152; int rem = i - co*1152; int t = rem >> 7; int ci = rem & 127;
    float v = w[((size_t)co*128 + ci)*9 + t];
    __nv_bfloat16 h = __float2bfloat16(v);
    whi[i] = h;
    wlo[i] = __float2bfloat16(v - __bfloat162float(h));
}

__global__ void wtrans_dec1_bf16(const float* __restrict__ w,
                                 __nv_bfloat16* __restrict__ whi, __nv_bfloat16* __restrict__ wlo)
{
    int i = blockIdx.x * 256 + threadIdx.x;
    if (i >= 128*2304) return;
    int co = i / 2304; int k = i - co*2304;
    int kh, kw, ci;
    if (k < 256)       { kh = 1; kw = 1; ci = k; }
    else if (k < 768)  { int t = (k-256) >> 8; ci = (k-256) & 255; kh = 1; kw = t ? 2 : 0; }
    else if (k < 1280) { int t = (k-768) >> 8; ci = (k-768) & 255; kh = t ? 2 : 0; kw = 1; }
    else               { int t = (k-1280) >> 8; ci = (k-1280) & 255;
                         kh = (t < 2) ? 0 : 2; kw = (t & 1) ? 2 : 0; }
    float v = w[((size_t)ci*128 + co)*9 + kh*3 + kw];
    __nv_bfloat16 h = __float2bfloat16(v);
    whi[i] = h;
    wlo[i] = __float2bfloat16(v - __bfloat162float(h));
}

__global__ void table_kernel(const float* __restrict__ pw, const float* __restrict__ pb,
                             const float* __restrict__ cb,
                             __nv_bfloat16* __restrict__ thi, __nv_bfloat16* __restrict__ tlo)
{
    __shared__ float c_s[64];
    int k = blockIdx.x, co = threadIdx.x;
    if (co < 64) c_s[co] = cb[k*64 + co];
    __syncthreads();
    float acc = pb[co];
#pragma unroll 8
    for (int ci = 0; ci < 64; ci++) acc += pw[co*64 + ci] * c_s[ci];
    __nv_bfloat16 h = __float2bfloat16(acc);
    thi[k*256 + co] = h;
    tlo[k*256 + co] = __float2bfloat16(acc - __bfloat162float(h));
}

// ---------------- conv1: 3->128, s2, NHWC output, f32x2 over co ----------------
__global__ void conv1_kernel(const float* __restrict__ x, const float* __restrict__ w,
                             const float* __restrict__ bias, float* __restrict__ out)
{
    __shared__ u64 w2_s[64*28];
    __shared__ float in_s[3*33*33];
    __shared__ float bias_s[128];
    int n = blockIdx.z;
    int OH0 = blockIdx.y * 16, OW0 = blockIdx.x * 16;
    int tid = threadIdx.x;
    for (int e = tid; e < 64*28; e += 256) {
        int cp = e / 28, t = e - cp*28;
        float v0 = (t < 27) ? w[(2*cp)*27 + t] : 0.f;
        float v1 = (t < 27) ? w[(2*cp+1)*27 + t] : 0.f;
        w2_s[e] = pack2(v0, v1);
    }
    for (int i = tid; i < 128; i += 256) bias_s[i] = bias[i];
    int IH0 = OH0*2 - 1, IW0 = OW0*2 - 1;
    for (int i = tid; i < 3*33*33; i += 256) {
        int ci = i / 1089; int r = (i % 1089) / 33; int c = i % 33;
        int ih = IH0 + r, iw = IW0 + c;
        float v = 0.f;
        if (ih >= 0 && ih < 128 && iw >= 0 && iw < 128) v = x[((n*3 + ci)*128 + ih)*128 + iw];
        in_s[i] = v;
    }
    __syncthreads();
    int ty = tid >> 4, tx = tid & 15;
    u64 in2[28];
#pragma unroll
    for (int ci = 0; ci < 3; ci++)
#pragma unroll
        for (int kh = 0; kh < 3; kh++)
#pragma unroll
            for (int kw = 0; kw < 3; kw++) {
                float f = in_s[ci*1089 + (ty*2+kh)*33 + (tx*2+kw)];
                in2[ci*9 + kh*3 + kw] = pack2(f, f);
            }
    in2[27] = 0ull;
    int oh = OH0 + ty, ow = OW0 + tx;
    float* outp = out + (((size_t)n*64 + oh)*64 + ow)*128;
    float4 buf;
    for (int cp = 0; cp < 64; cp++) {
        const ulonglong2* wp = reinterpret_cast<const ulonglong2*>(w2_s + cp*28);
        u64 a0 = 0ull, a1 = 0ull;
#pragma unroll
        for (int u = 0; u < 14; u++) {
            ulonglong2 ww = wp[u];
            a0 = fma2(ww.x, in2[2*u],   a0);
            a1 = fma2(ww.y, in2[2*u+1], a1);
        }
        float2 r = unpack2(add2(a0, a1));
        r.x += bias_s[2*cp]; r.y += bias_s[2*cp+1];
        if (cp & 1) {
            buf.z = r.x; buf.w = r.y;
            *reinterpret_cast<float4*>(outp + (cp-1)*2) = buf;
        } else {
            buf.x = r.x; buf.y = r.y;
        }
    }
}

// ---------------- BN stats NHWC (for h1) ----------------
__global__ void bn_stats_nhwc(const float* __restrict__ x, float* __restrict__ psum,
                              float* __restrict__ psq, int nblk)
{
    int blk = blockIdx.x;
    int cg = threadIdx.x & 31;
    int rg = threadIdx.x >> 5;
    float4 s = make_float4(0,0,0,0), sq = make_float4(0,0,0,0);
    for (int r = blk*8 + rg; r < 262144; r += nblk*8) {
        float4 v = *reinterpret_cast<const float4*>(x + (size_t)r*128 + cg*4);
        s.x += v.x; s.y += v.y; s.z += v.z; s.w += v.w;
        sq.x += v.x*v.x; sq.y += v.y*v.y; sq.z += v.z*v.z; sq.w += v.w*v.w;
    }
    __shared__ float ss[256*4], qs[256*4];
    reinterpret_cast<float4*>(ss)[threadIdx.x] = s;
    reinterpret_cast<float4*>(qs)[threadIdx.x] = sq;
    __syncthreads();
    if (threadIdx.x < 128) {
        int c = threadIdx.x;
        int cgi = c >> 2, j = c & 3;
        float a = 0.f, b = 0.f;
        for (int g = 0; g < 8; g++) { a += ss[(g*32+cgi)*4 + j]; b += qs[(g*32+cgi)*4 + j]; }
        psum[c*nblk + blk] = a;
        psq[c*nblk + blk] = b;
    }
}

// ---------------- parallel BN finalize ----------------
__global__ void bn_finalize_par(const float* __restrict__ psum, const float* __restrict__ psq,
                                const float* __restrict__ g, const float* __restrict__ b,
                                float* __restrict__ scale, float* __restrict__ shift,
                                int nblk, float inv_count)
{
    int c = blockIdx.x;
    int tid = threadIdx.x;
    float s = 0.f, sq = 0.f;
    for (int i = tid; i < nblk; i += 256) { s += psum[c*nblk + i]; sq += psq[c*nblk + i]; }
    __shared__ float rs[256], rq[256];
    rs[tid] = s; rq[tid] = sq;
    __syncthreads();
    for (int o = 128; o > 0; o >>= 1) {
        if (tid < o) { rs[tid] += rs[tid+o]; rq[tid] += rq[tid+o]; }
        __syncthreads();
    }
    if (tid == 0) {
        float mean = rs[0] * inv_count;
        float var = rq[0] * inv_count - mean*mean;
        float r = rsqrtf(var + 1e-5f);
        float sc = g[c] * r;
        scale[c] = sc;
        shift[c] = b[c] - mean * sc;
    }
}

// ---------------- BN+ReLU + bf16 split (vectorized) ----------------
__global__ void bnrelu_split_kernel(const float* __restrict__ x,
                                    __nv_bfloat16* __restrict__ hi, __nv_bfloat16* __restrict__ lo,
                                    const float* __restrict__ sc, const float* __restrict__ sh)
{
    long i = (long)blockIdx.x * 256 + threadIdx.x;
    if (i >= 8388608L) return;
    int cg = (int)(i & 31);
    float4 scv = reinterpret_cast<const float4*>(sc)[cg];
    float4 shv = reinterpret_cast<const float4*>(sh)[cg];
    float4 v = reinterpret_cast<const float4*>(x)[i];
    float r0 = fmaxf(fmaf(v.x, scv.x, shv.x), 0.f);
    float r1 = fmaxf(fmaf(v.y, scv.y, shv.y), 0.f);
    float r2 = fmaxf(fmaf(v.z, scv.z, shv.z), 0.f);
    float r3 = fmaxf(fmaf(v.w, scv.w, shv.w), 0.f);
    __nv_bfloat16 h0 = __float2bfloat16(r0), h1 = __float2bfloat16(r1);
    __nv_bfloat16 h2 = __float2bfloat16(r2), h3 = __float2bfloat16(r3);
    __nv_bfloat16 l0 = __float2bfloat16(r0 - __bfloat162float(h0));
    __nv_bfloat16 l1 = __float2bfloat16(r1 - __bfloat162float(h1));
    __nv_bfloat16 l2 = __float2bfloat16(r2 - __bfloat162float(h2));
    __nv_bfloat16 l3 = __float2bfloat16(r3 - __bfloat162float(h3));
    __nv_bfloat162 hp0(h0, h1), hp1(h2, h3), lp0(l0, l1), lp1(l2, l3);
    uint2 hv = make_uint2(*reinterpret_cast<uint32_t*>(&hp0), *reinterpret_cast<uint32_t*>(&hp1));
    uint2 lv = make_uint2(*reinterpret_cast<uint32_t*>(&lp0), *reinterpret_cast<uint32_t*>(&lp1));
    reinterpret_cast<uint2*>(hi)[i] = hv;
    reinterpret_cast<uint2*>(lo)[i] = lv;
}

// ---------------- gather: dhi/dlo[pos][256] = table[idx[pos]] ----------------
__global__ void gather_d(const float* __restrict__ idx_f,
                         const uint4* __restrict__ thi, const uint4* __restrict__ tlo,
                         uint4* __restrict__ dhi, uint4* __restrict__ dlo)
{
    int tid = threadIdx.x;
    int pos = blockIdx.x*32 + (tid >> 3);
    int c = tid & 7;
    int k = (int)idx_f[pos];
#pragma unroll
    for (int j = 0; j < 4; j++) {
        dhi[(size_t)pos*32 + c + j*8] = thi[k*32 + c + j*8];
        dlo[(size_t)pos*32 + c + j*8] = tlo[k*32 + c + j*8];
    }
}

// ---------------- conv2 via mma.sync bf16 split, N=64 tile, 2 CTAs/SM ----------------
#define C2A 16384u
#define C2B 8192u
#define C2STAGE (2u*C2A + 2u*C2B)    // 49152
__global__ void __launch_bounds__(256, 2) conv2_mma_kernel(
        const __nv_bfloat16* __restrict__ inhi, const __nv_bfloat16* __restrict__ inlo,
        const __nv_bfloat16* __restrict__ whi, const __nv_bfloat16* __restrict__ wlo,
        const float* __restrict__ bias, float* __restrict__ out)
{
    extern __shared__ char dsm[];
    __shared__ float bias_s[64];
    int mt = blockIdx.x, Nt = blockIdx.y, n = blockIdx.z;
    int OH0 = mt * 4;
    int tid = threadIdx.x, wid = tid >> 5, lane = tid & 31;
    int mrow = (wid >> 1) * 32;
    int ncol = (wid & 1) * 32;

    uint32_t base0 = ((uint32_t)__cvta_generic_to_shared(dsm) + 1023u) & ~1023u;
    for (int i = tid; i < 64; i += 256) bias_s[i] = bias[Nt*64 + i];

    auto fill = [&](int kc, int buf) {
        int t = kc >> 1, ci0 = (kc & 1) << 6;
        int kh = t / 3, kw = t - (t/3)*3;
        uint32_t Ah = base0 + buf*C2STAGE;
        uint32_t Al = Ah + C2A;
        uint32_t Bh = Al + C2A;
        uint32_t Bl = Bh + C2B;
        for (int i = tid; i < 1024; i += 256) {
            int px = i >> 3, c16 = i & 7;
            int oh = OH0 + (px >> 5), ow = px & 31;
            int ih = 2*oh - 1 + kh, iw = 2*ow - 1 + kw;
            bool ok = (ih >= 0) && (ih < 64) && (iw >= 0) && (iw < 64);
            long off = ((long)(n*64 + (ok ? ih : 0))*64 + (ok ? iw : 0))*128 + ci0 + c16*8;
            uint32_t d = SWZ(px*128 + c16*16);
            cp16z(Ah + d, inhi + off, ok);
            cp16z(Al + d, inlo + off, ok);
        }
        for (int i = tid; i < 512; i += 256) {
            int co = i >> 3, c16 = i & 7;
            long off = (long)(Nt*64 + co)*1152 + t*128 + ci0 + c16*8;
            uint32_t d = SWZ(co*128 + c16*16);
            cp16(Bh + d, whi + off);
            cp16(Bl + d, wlo + off);
        }
    };

    float acc[2][4][4];
#pragma unroll
    for (int a = 0; a < 2; a++)
#pragma unroll
        for (int b = 0; b < 4; b++)
#pragma unroll
            for (int c = 0; c < 4; c++) acc[a][b][c] = 0.f;

    fill(0, 0); CP_COMMIT();
    for (int s = 0; s < 18; s++) {
        if (s < 17) { fill(s+1, (s+1)&1); CP_COMMIT(); CP_WAIT(1); }
        else        { CP_WAIT(0); }
        __syncthreads();
        uint32_t Ah = base0 + (s&1)*C2STAGE;
        uint32_t Al = Ah + C2A;
        uint32_t Bh = Al + C2A;
        uint32_t Bl = Bh + C2B;
#pragma unroll
        for (int ks = 0; ks < 4; ks++) {
            uint32_t ah[2][4], al[2][4], bh[2][4], bl[2][4];
#pragma unroll
            for (int mi = 0; mi < 2; mi++) {
                int row = mrow + mi*16 + (lane & 15);
                uint32_t ao = SWZ(row*128 + ks*32 + (lane >> 4)*16);
                ldsm4(ah[mi], Ah + ao);
                ldsm4(al[mi], Al + ao);
            }
#pragma unroll
            for (int nb = 0; nb < 2; nb++) {
                int g = lane >> 3, r = lane & 7;
                int co_l = ncol + nb*16 + ((g >> 1) << 3) + r;
                uint32_t bo = SWZ(co_l*128 + ks*32 + (g & 1)*16);
                ldsm4(bh[nb], Bh + bo);
                ldsm4(bl[nb], Bl + bo);
            }
#pragma unroll
            for (int mi = 0; mi < 2; mi++)
#pragma unroll
                for (int nt = 0; nt < 4; nt++) {
                    const uint32_t* pbh = &bh[nt >> 1][(nt & 1)*2];
                    const uint32_t* pbl = &bl[nt >> 1][(nt & 1)*2];
                    mma16816(acc[mi][nt], ah[mi], pbh);
                    mma16816(acc[mi][nt], ah[mi], pbl);
                    mma16816(acc[mi][nt], al[mi], pbh);
                }
        }
        __syncthreads();
    }

    float* osm = reinterpret_cast<float*>(dsm);   // [64 co][132]
#pragma unroll
    for (int mi = 0; mi < 2; mi++)
#pragma unroll
        for (int nt = 0; nt < 4; nt++) {
            int px0 = mrow + mi*16 + (lane >> 2);
            int col = ncol + nt*8 + (lane & 3)*2;
            osm[col*132 + px0]         = acc[mi][nt][0];
            osm[(col+1)*132 + px0]     = acc[mi][nt][1];
            osm[col*132 + px0 + 8]     = acc[mi][nt][2];
            osm[(col+1)*132 + px0 + 8] = acc[mi][nt][3];
        }
    __syncthreads();
    for (int i = tid; i < 64*32; i += 256) {
        int co = i >> 5, p4 = (i & 31)*4;
        float4 v = *reinterpret_cast<const float4*>(osm + co*132 + p4);
        float b = bias_s[co];
        v.x += b; v.y += b; v.z += b; v.w += b;
        int cog = Nt*64 + co;
        *reinterpret_cast<float4*>(out + ((size_t)(n*256 + cog))*1024 + OH0*32 + p4) = v;
    }
}

// ---------------- dec1 via mma.sync bf16 split, N=64 tile, 2 CTAs/SM, fused BN partials ----------------
__global__ void __launch_bounds__(256, 2) dec1_mma_kernel(
        const __nv_bfloat16* __restrict__ inhi, const __nv_bfloat16* __restrict__ inlo,
        const __nv_bfloat16* __restrict__ whi, const __nv_bfloat16* __restrict__ wlo,
        const float* __restrict__ bias, float* __restrict__ out,
        float* __restrict__ psum, float* __restrict__ psq)
{
    extern __shared__ char dsm[];
    __shared__ float bias_s[64];
    __shared__ float sred[256], qred[256];
    const int NKC[4]  = {4, 8, 8, 16};
    const int KOFS[4] = {0, 256, 768, 1280};
    const int DYT[4][4] = {{0,0,0,0},{0,0,0,0},{1,0,0,0},{1,1,0,0}};
    const int DXT[4][4] = {{0,0,0,0},{1,0,0,0},{0,0,0,0},{1,0,1,0}};

    int mt = blockIdx.x, n = blockIdx.z;
    int cls = blockIdx.y >> 1, coH = blockIdx.y & 1;
    int ph = cls >> 1, pw = cls & 1;
    int Y0 = mt * 4;
    int tid = threadIdx.x, wid = tid >> 5, lane = tid & 31;
    int mrow = (wid >> 1) * 32;
    int ncol = (wid & 1) * 32;

    uint32_t base0 = ((uint32_t)__cvta_generic_to_shared(dsm) + 1023u) & ~1023u;
    for (int i = tid; i < 64; i += 256) bias_s[i] = bias[coH*64 + i];

    int kbase = KOFS[cls];
    int nk = NKC[cls];

    auto fill = [&](int kc, int buf) {
        int t = kc >> 2, ci0 = (kc & 3) << 6;
        int dy = DYT[cls][t], dx = DXT[cls][t];
        uint32_t Ah = base0 + buf*C2STAGE;
        uint32_t Al = Ah + C2A;
        uint32_t Bh = Al + C2A;
        uint32_t Bl = Bh + C2B;
        for (int i = tid; i < 1024; i += 256) {
            int px = i >> 3, c16 = i & 7;
            int y = Y0 + (px >> 5), x = px & 31;
            int iy = y + dy, ix = x + dx;
            bool ok = (iy < 32) && (ix < 32);
            long off = ((long)(n*32 + (ok ? iy : 0))*32 + (ok ? ix : 0))*256 + ci0 + c16*8;
            uint32_t d = SWZ(px*128 + c16*16);
            cp16z(Ah + d, inhi + off, ok);
            cp16z(Al + d, inlo + off, ok);
        }
        for (int i = tid; i < 512; i += 256) {
            int co = i >> 3, c16 = i & 7;
            long off = (long)(coH*64 + co)*2304 + kbase + t*256 + ci0 + c16*8;
            uint32_t d = SWZ(co*128 + c16*16);
            cp16(Bh + d, whi + off);
            cp16(Bl + d, wlo + off);
        }
    };

    float acc[2][4][4];
#pragma unroll
    for (int a = 0; a < 2; a++)
#pragma unroll
        for (int b = 0; b < 4; b++)
#pragma unroll
            for (int c = 0; c < 4; c++) acc[a][b][c] = 0.f;

    fill(0, 0); CP_COMMIT();
    for (int s = 0; s < nk; s++) {
        if (s < nk-1) { fill(s+1, (s+1)&1); CP_COMMIT(); CP_WAIT(1); }
        else          { CP_WAIT(0); }
        __syncthreads();
        uint32_t Ah = base0 + (s&1)*C2STAGE;
        uint32_t Al = Ah + C2A;
        uint32_t Bh = Al + C2A;
        uint32_t Bl = Bh + C2B;
#pragma unroll
        for (int ks = 0; ks < 4; ks++) {
            uint32_t ah[2][4], al[2][4], bh[2][4], bl[2][4];
#pragma unroll
            for (int mi = 0; mi < 2; mi++) {
                int row = mrow + mi*16 + (lane & 15);
                uint32_t ao = SWZ(row*128 + ks*32 + (lane >> 4)*16);
                ldsm4(ah[mi], Ah + ao);
                ldsm4(al[mi], Al + ao);
            }
#pragma unroll
            for (int nb = 0; nb < 2; nb++) {
                int g = lane >> 3, r = lane & 7;
                int co_l = ncol + nb*16 + ((g >> 1) << 3) + r;
                uint32_t bo = SWZ(co_l*128 + ks*32 + (g & 1)*16);
                ldsm4(bh[nb], Bh + bo);
                ldsm4(bl[nb], Bl + bo);
            }
#pragma unroll
            for (int mi = 0; mi < 2; mi++)
#pragma unroll
                for (int nt = 0; nt < 4; nt++) {
                    const uint32_t* pbh = &bh[nt >> 1][(nt & 1)*2];
                    const uint32_t* pbl = &bl[nt >> 1][(nt & 1)*2];
                    mma16816(acc[mi][nt], ah[mi], pbh);
                    mma16816(acc[mi][nt], ah[mi], pbl);
                    mma16816(acc[mi][nt], al[mi], pbh);
                }
        }
        __syncthreads();
    }

    float* osm = reinterpret_cast<float*>(dsm);   // [64 co][133]
#pragma unroll
    for (int mi = 0; mi < 2; mi++)
#pragma unroll
        for (int nt = 0; nt < 4; nt++) {
            int px0 = mrow + mi*16 + (lane >> 2);
            int col = ncol + nt*8 + (lane & 3)*2;
            osm[col*133 + px0]         = acc[mi][nt][0];
            osm[(col+1)*133 + px0]     = acc[mi][nt][1];
            osm[col*133 + px0 + 8]     = acc[mi][nt][2];
            osm[(col+1)*133 + px0 + 8] = acc[mi][nt][3];
        }
    __syncthreads();
    for (int i = tid; i < 64*128; i += 256) {
        int co = i >> 7, p = i & 127;
        int y = Y0 + (p >> 5), x = p & 31;
        int oh = 2*y + ph, ow = 2*x + pw;
        out[((size_t)(n*128 + coH*64 + co)*64 + oh)*64 + ow] = osm[co*133 + p] + bias_s[co];
    }
    // fused BN partial stats: 64 channels x 128 px, 4 quarters of 32 px
    {
        int co = tid & 63, quarter = tid >> 6;
        float s = 0.f, sq = 0.f;
        const float* op = osm + co*133 + quarter*32;
        float b = bias_s[co];
#pragma unroll 8
        for (int j = 0; j < 32; j++) {
            float v = op[j] + b;
            s += v; sq += v*v;
        }
        sred[tid] = s; qred[tid] = sq;
        __syncthreads();
        if (tid < 64) {
            int blk = blockIdx.x + 8*cls + 32*blockIdx.z;   // 0..2047
            int c = coH*64 + tid;
            psum[c*2048 + blk] = sred[tid] + sred[tid + 64] + sred[tid + 128] + sred[tid + 192];
            psq[c*2048 + blk]  = qred[tid] + qred[tid + 64] + qred[tid + 128] + qred[tid + 192];
        }
    }
}

// ---------------- pre 1x1: 256->64, f32x2 (split halves) ----------------
__global__ void pre_kernel(const float* __restrict__ in, const float* __restrict__ w,
                           const float* __restrict__ bias, float* __restrict__ out)
{
    __shared__ float w_t[256*32];
    int n = blockIdx.z, coH = blockIdx.y;
    int s = blockIdx.x * 256 + threadIdx.x;
    for (int i = threadIdx.x; i < 256*32; i += 256) {
        int ci = i >> 5, co = i & 31;
        w_t[i] = w[(size_t)(coH*32 + co)*256 + ci];
    }
    __syncthreads();
    u64 acc[16];
#pragma unroll
    for (int k = 0; k < 16; k++) acc[k] = 0ull;
    const float* ip = in + (size_t)n*256*1024 + s;
#pragma unroll 4
    for (int ci = 0; ci < 256; ci++) {
        float v = ip[(size_t)ci*1024];
        u64 pv = pack2(v, v);
        const ulonglong2* wp = reinterpret_cast<const ulonglong2*>(w_t + ci*32);
#pragma unroll
        for (int k = 0; k < 8; k++) {
            ulonglong2 ww = wp[k];
            acc[2*k]   = fma2(ww.x, pv, acc[2*k]);
            acc[2*k+1] = fma2(ww.y, pv, acc[2*k+1]);
        }
    }
    float* op = out + (size_t)n*64*1024 + (size_t)coH*32*1024 + s;
#pragma unroll
    for (int k = 0; k < 16; k++) {
        float2 v = unpack2(acc[k]);
        op[(size_t)(2*k  )*1024] = v.x + bias[coH*32 + 2*k];
        op[(size_t)(2*k+1)*1024] = v.y + bias[coH*32 + 2*k+1];
    }
}

// ---------------- VQ: 2 positions per thread ----------------
__global__ void vq_kernel(const float* __restrict__ z, const float* __restrict__ cb,
                          float* __restrict__ idx_out, float* __restrict__ losspart)
{
    extern __shared__ float sm[];
    float* cb_s = sm;
    float* csq  = sm + NCODE*VQ_DIM;
    int tid = threadIdx.x;
    for (int i = tid; i < NCODE*VQ_DIM; i += 256) cb_s[i] = cb[i];
    __syncthreads();
    for (int k = tid; k < NCODE; k += 256) {
        float s = 0.f;
#pragma unroll
        for (int d = 0; d < VQ_DIM; d++) { float c = cb_s[k*VQ_DIM + d]; s += c*c; }
        csq[k] = s;
    }
    __syncthreads();

    int s0 = blockIdx.x * 512 + tid;
    int s1 = s0 + 256;
    int bA = s0 >> 10, hwA = s0 & 1023;
    int bB = s1 >> 10, hwB = s1 & 1023;
    const float* zpA = z + (size_t)bA*64*1024 + hwA;
    const float* zpB = z + (size_t)bB*64*1024 + hwB;
    u64 zA[32], zB[32];
    float zsqA = 0.f, zsqB = 0.f;
#pragma unroll
    for (int u = 0; u < 32; u++) {
        float a0 = zpA[(size_t)(2*u)*1024], a1 = zpA[(size_t)(2*u+1)*1024];
        float b0 = zpB[(size_t)(2*u)*1024], b1 = zpB[(size_t)(2*u+1)*1024];
        zsqA += a0*a0 + a1*a1;
        zsqB += b0*b0 + b1*b1;
        zA[u] = pack2(a0, a1);
        zB[u] = pack2(b0, b1);
    }

    float bestA = 3.4e38f, bestB = 3.4e38f;
    int idxA = 0, idxB = 0;
    for (int k = 0; k < NCODE; k++) {
        const ulonglong2* cp2 = reinterpret_cast<const ulonglong2*>(cb_s + k*VQ_DIM);
        u64 dA0 = 0ull, dA1 = 0ull, dB0 = 0ull, dB1 = 0ull;
#pragma unroll
        for (int u = 0; u < 16; u++) {
            ulonglong2 c2 = cp2[u];
            dA0 = fma2(c2.x, zA[2*u],   dA0);
            dA1 = fma2(c2.y, zA[2*u+1], dA1);
            dB0 = fma2(c2.x, zB[2*u],   dB0);
            dB1 = fma2(c2.y, zB[2*u+1], dB1);
        }
        float2 da = unpack2(add2(dA0, dA1));
        float2 db = unpack2(add2(dB0, dB1));
        float cq = csq[k];
        float distA = zsqA - 2.f*(da.x + da.y) + cq;
        float distB = zsqB - 2.f*(db.x + db.y) + cq;
        if (distA < bestA) { bestA = distA; idxA = k; }
        if (distB < bestB) { bestB = distB; idxB = k; }
    }

    float lsum = 0.f;
#pragma unroll
    for (int u = 0; u < 32; u++) {
        float2 za = unpack2(zA[u]);
        float2 zb = unpack2(zB[u]);
        float ca0 = cb_s[idxA*VQ_DIM + 2*u], ca1 = cb_s[idxA*VQ_DIM + 2*u+1];
        float cb0 = cb_s[idxB*VQ_DIM + 2*u], cb1 = cb_s[idxB*VQ_DIM + 2*u+1];
        float dA0 = za.x - ca0, dA1 = za.y - ca1;
        float dB0 = zb.x - cb0, dB1 = zb.y - cb1;
        lsum += dA0*dA0 + dA1*dA1 + dB0*dB0 + dB1*dB1;
    }
    idx_out[s0] = (float)idxA;
    idx_out[s1] = (float)idxB;

    __shared__ float red[256];
    red[tid] = lsum; __syncthreads();
    for (int o = 128; o > 0; o >>= 1) {
        if (tid < o) red[tid] += red[tid + o];
        __syncthreads();
    }
    if (tid == 0) losspart[blockIdx.x] = red[0];
}

__global__ void loss_finalize_kernel(const float* __restrict__ losspart,
                                     float* __restrict__ out_losses)
{
    __shared__ float red[256];
    red[threadIdx.x] = (threadIdx.x < 128) ? losspart[threadIdx.x] : 0.f;
    __syncthreads();
    for (int o = 128; o > 0; o >>= 1) {
        if (threadIdx.x < o) red[threadIdx.x] += red[threadIdx.x + o];
        __syncthreads();
    }
    if (threadIdx.x == 0) {
        float m = red[0] / (65536.f * 64.f);
        out_losses[0] = m;
        out_losses[1] = m;
    }
}

// ---------------- dec2 quad-centric, ci-split x4 ----------------
__global__ void dec2_kernel(const float* __restrict__ in, const float* __restrict__ w,
                            const float* __restrict__ bias, const float* __restrict__ scale,
                            const float* __restrict__ shift, float* __restrict__ out)
{
    extern __shared__ float sm[];
    float* w_s  = sm;
    float* in_s = sm + 3456;
    float* sc_s = sm + 17280;
    float* sh_s = sm + 17408;
    float* red  = sm + 17536;
    int n = blockIdx.y; int tile = blockIdx.x;
    int OH0 = (tile >> 3) * 16, OW0 = (tile & 7) * 16;
    int IH0 = OH0 >> 1, IW0 = OW0 >> 1;
    int tid = threadIdx.x;
    for (int i = tid; i < 3456; i += 256) w_s[i] = w[i];
    for (int i = tid; i < 128; i += 256) { sc_s[i] = scale[i]; sh_s[i] = shift[i]; }
    __syncthreads();
    for (int i = tid; i < 128*108; i += 256) {
        int ci = i / 108; int rem = i - ci*108; int rr = rem / 12; int cc = rem - rr*12;
        int ih = IH0 + rr, iw = IW0 + cc;
        float v = 0.f;
        if (cc < 9 && ih < 64 && iw < 64) {
            float raw = in[((size_t)(n*128 + ci)*64 + ih)*64 + iw];
            v = fmaxf(fmaf(raw, sc_s[ci], sh_s[ci]), 0.f);
        }
        in_s[i] = v;
    }
    __syncthreads();

    int q = tid & 63, qy = q >> 3, qx = q & 7;
    int cisub = tid >> 6;
    float acc[4][3];
#pragma unroll
    for (int p = 0; p < 4; p++)
#pragma unroll
        for (int co = 0; co < 3; co++) acc[p][co] = 0.f;

    int ci0 = cisub * 32;
#pragma unroll 4
    for (int ci = ci0; ci < ci0 + 32; ci++) {
        const float* base = in_s + ci*108 + qy*12 + qx;
        float v00 = base[0], v01 = base[1], v10 = base[12], v11 = base[13];
        const float* wp = w_s + ci*27;
#pragma unroll
        for (int co = 0; co < 3; co++) {
            const float* wc = wp + co*9;
            acc[0][co] += wc[4]*v00;
            acc[1][co] += wc[3]*v01 + wc[5]*v00;
            acc[2][co] += wc[1]*v10 + wc[7]*v00;
            acc[3][co] += wc[0]*v11 + wc[2]*v10 + wc[6]*v01 + wc[8]*v00;
        }
    }
#pragma unroll
    for (int p = 0; p < 4; p++)
#pragma unroll
        for (int co = 0; co < 3; co++)
            red[(p*3 + co)*256 + tid] = acc[p][co];
    __syncthreads();
    if (tid < 64) {
#pragma unroll
        for (int p = 0; p < 4; p++) {
            int ph = p >> 1, pw = p & 1;
            int oh = OH0 + 2*qy + ph, ow = OW0 + 2*qx + pw;
#pragma unroll
            for (int co = 0; co < 3; co++) {
                int j = p*3 + co;
                float s = red[j*256 + tid] + red[j*256 + tid + 64]
                        + red[j*256 + tid + 128] + red[j*256 + tid + 192];
                out[((size_t)(n*3 + co)*128 + oh)*128 + ow] = tanhf(s + bias[co]);
            }
        }
    }
}

// ---------------- host launch ----------------
static float* sym_addr(const void* sym)
{
    void* p = nullptr;
    cudaGetSymbolAddress(&p, sym);
    return (float*)p;
}

extern "C" void kernel_launch(void* const* d_in, const int* in_sizes, int n_in,
                              void* d_out, int out_size)
{
    const float* x       = (const float*)d_in[0];
    const float* enc1_w  = (const float*)d_in[1];
    const float* enc1_b  = (const float*)d_in[2];
    const float* bn1_g   = (const float*)d_in[3];
    const float* bn1_b   = (const float*)d_in[4];
    const float* enc2_w  = (const float*)d_in[5];
    const float* enc2_b  = (const float*)d_in[6];
    const float* pre_w   = (const float*)d_in[7];
    const float* pre_b   = (const float*)d_in[8];
    const float* codebook= (const float*)d_in[9];
    const float* post_w  = (const float*)d_in[10];
    const float* post_b  = (const float*)d_in[11];
    const float* dec1_w  = (const float*)d_in[12];
    const float* dec1_b  = (const float*)d_in[13];
    const float* dbn1_g  = (const float*)d_in[14];
    const float* dbn1_b  = (const float*)d_in[15];
    const float* dec2_w  = (const float*)d_in[16];
    const float* dec2_b  = (const float*)d_in[17];

    float* out = (float*)d_out;
    float* out_losses = out + RECON_ELEMS;
    float* out_idx    = out + RECON_ELEMS + 2;

    float* h1  = sym_addr(g_h1);
    __nv_bfloat16* h1hi; { void* p; cudaGetSymbolAddress(&p, g_h1hi); h1hi = (__nv_bfloat16*)p; }
    __nv_bfloat16* h1lo; { void* p; cudaGetSymbolAddress(&p, g_h1lo); h1lo = (__nv_bfloat16*)p; }
    __nv_bfloat16* w2chi; { void* p; cudaGetSymbolAddress(&p, g_w2chi); w2chi = (__nv_bfloat16*)p; }
    __nv_bfloat16* w2clo; { void* p; cudaGetSymbolAddress(&p, g_w2clo); w2clo = (__nv_bfloat16*)p; }
    __nv_bfloat16* wd1hi; { void* p; cudaGetSymbolAddress(&p, g_wd1hi); wd1hi = (__nv_bfloat16*)p; }
    __nv_bfloat16* wd1lo; { void* p; cudaGetSymbolAddress(&p, g_wd1lo); wd1lo = (__nv_bfloat16*)p; }
    __nv_bfloat16* dhi; { void* p; cudaGetSymbolAddress(&p, g_dhi); dhi = (__nv_bfloat16*)p; }
    __nv_bfloat16* dlo; { void* p; cudaGetSymbolAddress(&p, g_dlo); dlo = (__nv_bfloat16*)p; }
    __nv_bfloat16* tabhi; { void* p; cudaGetSymbolAddress(&p, g_tabhi); tabhi = (__nv_bfloat16*)p; }
    __nv_bfloat16* tablo; { void* p; cudaGetSymbolAddress(&p, g_tablo); tablo = (__nv_bfloat16*)p; }
    float* h2  = sym_addr(g_h2);
    float* z   = sym_addr(g_z);
    float* d1  = sym_addr(g_d1);
    float* psum = sym_addr(g_psum);
    float* psq  = sym_addr(g_psq);
    float* sc   = sym_addr(g_scale);
    float* sh   = sym_addr(g_shift);
    float* lp   = sym_addr(g_losspart);

    const unsigned GEMM_SMEM = 2*C2STAGE + 1024;   // 99328 -> 2 CTAs/SM
    cudaFuncSetAttribute(conv2_mma_kernel, cudaFuncAttributeMaxDynamicSharedMemorySize, GEMM_SMEM);
    cudaFuncSetAttribute(dec1_mma_kernel,  cudaFuncAttributeMaxDynamicSharedMemorySize, GEMM_SMEM);
    cudaFuncSetAttribute(vq_kernel,   cudaFuncAttributeMaxDynamicSharedMemorySize, 133120);
    cudaFuncSetAttribute(dec2_kernel, cudaFuncAttributeMaxDynamicSharedMemorySize, 84480);

    const float inv_cnt = 1.f / 262144.f;

    conv1_kernel<<<dim3(4,4,64), 256>>>(x, enc1_w, enc1_b, h1);
    bn_stats_nhwc<<<1024, 256>>>(h1, psum, psq, 1024);
    bn_finalize_par<<<128, 256>>>(psum, psq, bn1_g, bn1_b, sc, sh, 1024, inv_cnt);
    bnrelu_split_kernel<<<32768, 256>>>(h1, h1hi, h1lo, sc, sh);
    wtrans_conv2_bf16<<<1152, 256>>>(enc2_w, w2chi, w2clo);
    conv2_mma_kernel<<<dim3(8,4,64), 256, GEMM_SMEM>>>(h1hi, h1lo, w2chi, w2clo, enc2_b, h2);
    wtrans_dec1_bf16<<<1152, 256>>>(dec1_w, wd1hi, wd1lo);
    table_kernel<<<512, 256>>>(post_w, post_b, codebook, tabhi, tablo);
    pre_kernel<<<dim3(4,2,64), 256>>>(h2, pre_w, pre_b, z);

    vq_kernel<<<128, 256, 133120>>>(z, codebook, out_idx, lp);
    loss_finalize_kernel<<<1,256>>>(lp, out_losses);
    gather_d<<<2048, 256>>>(out_idx, (const uint4*)tabhi, (const uint4*)tablo,
                            (uint4*)dhi, (uint4*)dlo);

    dec1_mma_kernel<<<dim3(8,8,64), 256, GEMM_SMEM>>>(dhi, dlo, wd1hi, wd1lo, dec1_b, d1, psum, psq);
    bn_finalize_par<<<128, 256>>>(psum, psq, dbn1_g, dbn1_b, sc, sh, 2048, inv_cnt);
    dec2_kernel<<<dim3(64,64), 256, 84480>>>(d1, dec2_w, dec2_b, sc, sh, out);

    (void)in_sizes; (void)n_in; (void)out_size;
}

// round 15
// speedup vs baseline: 1.2342x; 1.2342x over previous
#include <cuda_runtime.h>
#include <cuda_bf16.h>
#include <cstdint>

#define H1_ELEMS (64*128*64*64)
#define H2_ELEMS (64*256*32*32)
#define Z_ELEMS  (64*64*32*32)
#define D_ELEMS  (64*256*32*32)
#define D1_ELEMS (64*128*64*64)
#define RECON_ELEMS (64*3*128*128)
#define VQ_DIM 64
#define NCODE 512

__device__ float g_h1[H1_ELEMS];                 // NHWC fp32
__device__ __nv_bfloat16 g_h1hi[H1_ELEMS];
__device__ __nv_bfloat16 g_h1lo[H1_ELEMS];
__device__ float g_h2[H2_ELEMS];
__device__ float g_z[Z_ELEMS];
__device__ __nv_bfloat16 g_dhi[D_ELEMS];
__device__ __nv_bfloat16 g_dlo[D_ELEMS];
__device__ float g_d1[D1_ELEMS];
__device__ __nv_bfloat16 g_w2chi[256*1152];
__device__ __nv_bfloat16 g_w2clo[256*1152];
__device__ __nv_bfloat16 g_wd1hi[128*2304];
__device__ __nv_bfloat16 g_wd1lo[128*2304];
__device__ __nv_bfloat16 g_tabhi[NCODE*256];
__device__ __nv_bfloat16 g_tablo[NCODE*256];
__device__ float g_psum[128*2048];
__device__ float g_psq[128*2048];
__device__ float g_scale[128];
__device__ float g_shift[128];
__device__ float g_losspart[256];

typedef unsigned long long u64;
__device__ __forceinline__ u64 pack2(float a, float b) {
    u64 r; asm("mov.b64 %0, {%1,%2};" : "=l"(r) : "f"(a), "f"(b)); return r;
}
__device__ __forceinline__ u64 fma2(u64 a, u64 b, u64 c) {
    u64 d; asm("fma.rn.f32x2 %0, %1, %2, %3;" : "=l"(d) : "l"(a), "l"(b), "l"(c)); return d;
}
__device__ __forceinline__ u64 add2(u64 a, u64 b) {
    u64 d; asm("add.rn.f32x2 %0, %1, %2;" : "=l"(d) : "l"(a), "l"(b)); return d;
}
__device__ __forceinline__ float2 unpack2(u64 a) {
    float lo, hi; asm("mov.b64 {%0,%1}, %2;" : "=f"(lo), "=f"(hi) : "l"(a));
    return make_float2(lo, hi);
}
__device__ __forceinline__ void cp16(uint32_t saddr, const void* gaddr) {
    asm volatile("cp.async.cg.shared.global [%0], [%1], 16;" :: "r"(saddr), "l"(gaddr));
}
__device__ __forceinline__ void cp16z(uint32_t saddr, const void* gaddr, bool ok) {
    int sz = ok ? 16 : 0;
    asm volatile("cp.async.cg.shared.global [%0], [%1], 16, %2;" :: "r"(saddr), "l"(gaddr), "r"(sz));
}
#define CP_COMMIT() asm volatile("cp.async.commit_group;")
#define CP_WAIT(n)  asm volatile("cp.async.wait_group %0;" :: "n"(n))

#define SWZ(o) ((o) ^ ((((uint32_t)(o)) >> 3) & 0x70))

__device__ __forceinline__ void ldsm4(uint32_t* r, uint32_t addr) {
    asm volatile("ldmatrix.sync.aligned.m8n8.x4.shared.b16 {%0,%1,%2,%3}, [%4];"
                 : "=r"(r[0]), "=r"(r[1]), "=r"(r[2]), "=r"(r[3]) : "r"(addr));
}
__device__ __forceinline__ void mma16816(float* c, const uint32_t* a, const uint32_t* b) {
    asm volatile(
        "mma.sync.aligned.m16n8k16.row.col.f32.bf16.bf16.f32 "
        "{%0,%1,%2,%3}, {%4,%5,%6,%7}, {%8,%9}, {%0,%1,%2,%3};"
        : "+f"(c[0]), "+f"(c[1]), "+f"(c[2]), "+f"(c[3])
        : "r"(a[0]), "r"(a[1]), "r"(a[2]), "r"(a[3]), "r"(b[0]), "r"(b[1]));
}

// ---------------- weight prep ----------------
__global__ void wtrans_conv2_bf16(const float* __restrict__ w,
                                  __nv_bfloat16* __restrict__ whi, __nv_bfloat16* __restrict__ wlo)
{
    int i = blockIdx.x * 256 + threadIdx.x;
    if (i >= 256*1152) return;
    int co = i / 1152; int rem = i - co*1152; int t = rem >> 7; int ci = rem & 127;
    float v = w[((size_t)co*128 + ci)*9 + t];
    __nv_bfloat16 h = __float2bfloat16(v);
    whi[i] = h;
    wlo[i] = __float2bfloat16(v - __bfloat162float(h));
}

__global__ void wtrans_dec1_bf16(const float* __restrict__ w,
                                 __nv_bfloat16* __restrict__ whi, __nv_bfloat16* __restrict__ wlo)
{
    int i = blockIdx.x * 256 + threadIdx.x;
    if (i >= 128*2304) return;
    int co = i / 2304; int k = i - co*2304;
    int kh, kw, ci;
    if (k < 256)       { kh = 1; kw = 1; ci = k; }
    else if (k < 768)  { int t = (k-256) >> 8; ci = (k-256) & 255; kh = 1; kw = t ? 2 : 0; }
    else if (k < 1280) { int t = (k-768) >> 8; ci = (k-768) & 255; kh = t ? 2 : 0; kw = 1; }
    else               { int t = (k-1280) >> 8; ci = (k-1280) & 255;
                         kh = (t < 2) ? 0 : 2; kw = (t & 1) ? 2 : 0; }
    float v = w[((size_t)ci*128 + co)*9 + kh*3 + kw];
    __nv_bfloat16 h = __float2bfloat16(v);
    whi[i] = h;
    wlo[i] = __float2bfloat16(v - __bfloat162float(h));
}

__global__ void table_kernel(const float* __restrict__ pw, const float* __restrict__ pb,
                             const float* __restrict__ cb,
                             __nv_bfloat16* __restrict__ thi, __nv_bfloat16* __restrict__ tlo)
{
    __shared__ float c_s[64];
    int k = blockIdx.x, co = threadIdx.x;
    if (co < 64) c_s[co] = cb[k*64 + co];
    __syncthreads();
    float acc = pb[co];
#pragma unroll 8
    for (int ci = 0; ci < 64; ci++) acc += pw[co*64 + ci] * c_s[ci];
    __nv_bfloat16 h = __float2bfloat16(acc);
    thi[k*256 + co] = h;
    tlo[k*256 + co] = __float2bfloat16(acc - __bfloat162float(h));
}

// ---------------- conv1: 3->128, s2, NHWC output, f32x2 over co ----------------
__global__ void conv1_kernel(const float* __restrict__ x, const float* __restrict__ w,
                             const float* __restrict__ bias, float* __restrict__ out)
{
    __shared__ u64 w2_s[64*28];
    __shared__ float in_s[3*33*33];
    __shared__ float bias_s[128];
    int n = blockIdx.z;
    int OH0 = blockIdx.y * 16, OW0 = blockIdx.x * 16;
    int tid = threadIdx.x;
    for (int e = tid; e < 64*28; e += 256) {
        int cp = e / 28, t = e - cp*28;
        float v0 = (t < 27) ? w[(2*cp)*27 + t] : 0.f;
        float v1 = (t < 27) ? w[(2*cp+1)*27 + t] : 0.f;
        w2_s[e] = pack2(v0, v1);
    }
    for (int i = tid; i < 128; i += 256) bias_s[i] = bias[i];
    int IH0 = OH0*2 - 1, IW0 = OW0*2 - 1;
    for (int i = tid; i < 3*33*33; i += 256) {
        int ci = i / 1089; int r = (i % 1089) / 33; int c = i % 33;
        int ih = IH0 + r, iw = IW0 + c;
        float v = 0.f;
        if (ih >= 0 && ih < 128 && iw >= 0 && iw < 128) v = x[((n*3 + ci)*128 + ih)*128 + iw];
        in_s[i] = v;
    }
    __syncthreads();
    int ty = tid >> 4, tx = tid & 15;
    u64 in2[28];
#pragma unroll
    for (int ci = 0; ci < 3; ci++)
#pragma unroll
        for (int kh = 0; kh < 3; kh++)
#pragma unroll
            for (int kw = 0; kw < 3; kw++) {
                float f = in_s[ci*1089 + (ty*2+kh)*33 + (tx*2+kw)];
                in2[ci*9 + kh*3 + kw] = pack2(f, f);
            }
    in2[27] = 0ull;
    int oh = OH0 + ty, ow = OW0 + tx;
    float* outp = out + (((size_t)n*64 + oh)*64 + ow)*128;
    float4 buf;
    for (int cp = 0; cp < 64; cp++) {
        const ulonglong2* wp = reinterpret_cast<const ulonglong2*>(w2_s + cp*28);
        u64 a0 = 0ull, a1 = 0ull;
#pragma unroll
        for (int u = 0; u < 14; u++) {
            ulonglong2 ww = wp[u];
            a0 = fma2(ww.x, in2[2*u],   a0);
            a1 = fma2(ww.y, in2[2*u+1], a1);
        }
        float2 r = unpack2(add2(a0, a1));
        r.x += bias_s[2*cp]; r.y += bias_s[2*cp+1];
        if (cp & 1) {
            buf.z = r.x; buf.w = r.y;
            *reinterpret_cast<float4*>(outp + (cp-1)*2) = buf;
        } else {
            buf.x = r.x; buf.y = r.y;
        }
    }
}

// ---------------- BN stats NHWC (for h1) ----------------
__global__ void bn_stats_nhwc(const float* __restrict__ x, float* __restrict__ psum,
                              float* __restrict__ psq, int nblk)
{
    int blk = blockIdx.x;
    int cg = threadIdx.x & 31;
    int rg = threadIdx.x >> 5;
    float4 s = make_float4(0,0,0,0), sq = make_float4(0,0,0,0);
    for (int r = blk*8 + rg; r < 262144; r += nblk*8) {
        float4 v = *reinterpret_cast<const float4*>(x + (size_t)r*128 + cg*4);
        s.x += v.x; s.y += v.y; s.z += v.z; s.w += v.w;
        sq.x += v.x*v.x; sq.y += v.y*v.y; sq.z += v.z*v.z; sq.w += v.w*v.w;
    }
    __shared__ float ss[256*4], qs[256*4];
    reinterpret_cast<float4*>(ss)[threadIdx.x] = s;
    reinterpret_cast<float4*>(qs)[threadIdx.x] = sq;
    __syncthreads();
    if (threadIdx.x < 128) {
        int c = threadIdx.x;
        int cgi = c >> 2, j = c & 3;
        float a = 0.f, b = 0.f;
        for (int g = 0; g < 8; g++) { a += ss[(g*32+cgi)*4 + j]; b += qs[(g*32+cgi)*4 + j]; }
        psum[c*nblk + blk] = a;
        psq[c*nblk + blk] = b;
    }
}

// ---------------- parallel BN finalize ----------------
__global__ void bn_finalize_par(const float* __restrict__ psum, const float* __restrict__ psq,
                                const float* __restrict__ g, const float* __restrict__ b,
                                float* __restrict__ scale, float* __restrict__ shift,
                                int nblk, float inv_count)
{
    int c = blockIdx.x;
    int tid = threadIdx.x;
    float s = 0.f, sq = 0.f;
    for (int i = tid; i < nblk; i += 256) { s += psum[c*nblk + i]; sq += psq[c*nblk + i]; }
    __shared__ float rs[256], rq[256];
    rs[tid] = s; rq[tid] = sq;
    __syncthreads();
    for (int o = 128; o > 0; o >>= 1) {
        if (tid < o) { rs[tid] += rs[tid+o]; rq[tid] += rq[tid+o]; }
        __syncthreads();
    }
    if (tid == 0) {
        float mean = rs[0] * inv_count;
        float var = rq[0] * inv_count - mean*mean;
        float r = rsqrtf(var + 1e-5f);
        float sc = g[c] * r;
        scale[c] = sc;
        shift[c] = b[c] - mean * sc;
    }
}

// ---------------- BN+ReLU + bf16 split (vectorized) ----------------
__global__ void bnrelu_split_kernel(const float* __restrict__ x,
                                    __nv_bfloat16* __restrict__ hi, __nv_bfloat16* __restrict__ lo,
                                    const float* __restrict__ sc, const float* __restrict__ sh)
{
    long i = (long)blockIdx.x * 256 + threadIdx.x;
    if (i >= 8388608L) return;
    int cg = (int)(i & 31);
    float4 scv = reinterpret_cast<const float4*>(sc)[cg];
    float4 shv = reinterpret_cast<const float4*>(sh)[cg];
    float4 v = reinterpret_cast<const float4*>(x)[i];
    float r0 = fmaxf(fmaf(v.x, scv.x, shv.x), 0.f);
    float r1 = fmaxf(fmaf(v.y, scv.y, shv.y), 0.f);
    float r2 = fmaxf(fmaf(v.z, scv.z, shv.z), 0.f);
    float r3 = fmaxf(fmaf(v.w, scv.w, shv.w), 0.f);
    __nv_bfloat16 h0 = __float2bfloat16(r0), h1 = __float2bfloat16(r1);
    __nv_bfloat16 h2 = __float2bfloat16(r2), h3 = __float2bfloat16(r3);
    __nv_bfloat16 l0 = __float2bfloat16(r0 - __bfloat162float(h0));
    __nv_bfloat16 l1 = __float2bfloat16(r1 - __bfloat162float(h1));
    __nv_bfloat16 l2 = __float2bfloat16(r2 - __bfloat162float(h2));
    __nv_bfloat16 l3 = __float2bfloat16(r3 - __bfloat162float(h3));
    __nv_bfloat162 hp0(h0, h1), hp1(h2, h3), lp0(l0, l1), lp1(l2, l3);
    uint2 hv = make_uint2(*reinterpret_cast<uint32_t*>(&hp0), *reinterpret_cast<uint32_t*>(&hp1));
    uint2 lv = make_uint2(*reinterpret_cast<uint32_t*>(&lp0), *reinterpret_cast<uint32_t*>(&lp1));
    reinterpret_cast<uint2*>(hi)[i] = hv;
    reinterpret_cast<uint2*>(lo)[i] = lv;
}

// ---------------- gather: dhi/dlo[pos][256] = table[idx[pos]] ----------------
__global__ void gather_d(const float* __restrict__ idx_f,
                         const uint4* __restrict__ thi, const uint4* __restrict__ tlo,
                         uint4* __restrict__ dhi, uint4* __restrict__ dlo)
{
    int tid = threadIdx.x;
    int pos = blockIdx.x*32 + (tid >> 3);
    int c = tid & 7;
    int k = (int)idx_f[pos];
#pragma unroll
    for (int j = 0; j < 4; j++) {
        dhi[(size_t)pos*32 + c + j*8] = thi[k*32 + c + j*8];
        dlo[(size_t)pos*32 + c + j*8] = tlo[k*32 + c + j*8];
    }
}

// ---------------- conv2 via mma.sync bf16 split, depth-2 (R13 config) ----------------
#define MM_SPLIT 16384u
#define MM_STAGE (4u*MM_SPLIT)
__global__ void __launch_bounds__(256, 1) conv2_mma_kernel(
        const __nv_bfloat16* __restrict__ inhi, const __nv_bfloat16* __restrict__ inlo,
        const __nv_bfloat16* __restrict__ whi, const __nv_bfloat16* __restrict__ wlo,
        const float* __restrict__ bias, float* __restrict__ out)
{
    extern __shared__ char dsm[];
    __shared__ float bias_s[128];
    int mt = blockIdx.x, Nt = blockIdx.y, n = blockIdx.z;
    int OH0 = mt * 4;
    int tid = threadIdx.x, wid = tid >> 5, lane = tid & 31;
    int mrow = (wid >> 1) * 32;
    int ncol = (wid & 1) * 64;

    uint32_t base0 = ((uint32_t)__cvta_generic_to_shared(dsm) + 1023u) & ~1023u;
    for (int i = tid; i < 128; i += 256) bias_s[i] = bias[Nt*128 + i];

    auto fill = [&](int kc, int buf) {
        int t = kc >> 1, ci0 = (kc & 1) << 6;
        int kh = t / 3, kw = t - (t/3)*3;
        uint32_t Ah = base0 + buf*MM_STAGE;
        uint32_t Al = Ah + MM_SPLIT;
        uint32_t Bh = Al + MM_SPLIT;
        uint32_t Bl = Bh + MM_SPLIT;
        for (int i = tid; i < 1024; i += 256) {
            int px = i >> 3, c16 = i & 7;
            int oh = OH0 + (px >> 5), ow = px & 31;
            int ih = 2*oh - 1 + kh, iw = 2*ow - 1 + kw;
            bool ok = (ih >= 0) && (ih < 64) && (iw >= 0) && (iw < 64);
            long off = ((long)(n*64 + (ok ? ih : 0))*64 + (ok ? iw : 0))*128 + ci0 + c16*8;
            uint32_t d = SWZ(px*128 + c16*16);
            cp16z(Ah + d, inhi + off, ok);
            cp16z(Al + d, inlo + off, ok);
        }
        for (int i = tid; i < 1024; i += 256) {
            int co = i >> 3, c16 = i & 7;
            long off = (long)(Nt*128 + co)*1152 + t*128 + ci0 + c16*8;
            uint32_t d = SWZ(co*128 + c16*16);
            cp16(Bh + d, whi + off);
            cp16(Bl + d, wlo + off);
        }
    };

    float acc[2][8][4];
#pragma unroll
    for (int a = 0; a < 2; a++)
#pragma unroll
        for (int b = 0; b < 8; b++)
#pragma unroll
            for (int c = 0; c < 4; c++) acc[a][b][c] = 0.f;

    fill(0, 0); CP_COMMIT();
    for (int s = 0; s < 18; s++) {
        if (s < 17) { fill(s+1, (s+1)&1); CP_COMMIT(); CP_WAIT(1); }
        else        { CP_WAIT(0); }
        __syncthreads();
        uint32_t Ah = base0 + (s&1)*MM_STAGE;
        uint32_t Al = Ah + MM_SPLIT;
        uint32_t Bh = Al + MM_SPLIT;
        uint32_t Bl = Bh + MM_SPLIT;
#pragma unroll
        for (int ks = 0; ks < 4; ks++) {
            uint32_t ah[2][4], al[2][4], bh[4][4], bl[4][4];
#pragma unroll
            for (int mi = 0; mi < 2; mi++) {
                int row = mrow + mi*16 + (lane & 15);
                uint32_t ao = SWZ(row*128 + ks*32 + (lane >> 4)*16);
                ldsm4(ah[mi], Ah + ao);
                ldsm4(al[mi], Al + ao);
            }
#pragma unroll
            for (int nb = 0; nb < 4; nb++) {
                int g = lane >> 3, r = lane & 7;
                int co_l = ncol + nb*16 + ((g >> 1) << 3) + r;
                uint32_t bo = SWZ(co_l*128 + ks*32 + (g & 1)*16);
                ldsm4(bh[nb], Bh + bo);
                ldsm4(bl[nb], Bl + bo);
            }
#pragma unroll
            for (int mi = 0; mi < 2; mi++)
#pragma unroll
                for (int nt = 0; nt < 8; nt++) {
                    const uint32_t* pbh = &bh[nt >> 1][(nt & 1)*2];
                    const uint32_t* pbl = &bl[nt >> 1][(nt & 1)*2];
                    mma16816(acc[mi][nt], ah[mi], pbh);
                    mma16816(acc[mi][nt], ah[mi], pbl);
                    mma16816(acc[mi][nt], al[mi], pbh);
                }
        }
        __syncthreads();
    }

    float* osm = reinterpret_cast<float*>(dsm);
#pragma unroll
    for (int mi = 0; mi < 2; mi++)
#pragma unroll
        for (int nt = 0; nt < 8; nt++) {
            int px0 = mrow + mi*16 + (lane >> 2);
            int col = ncol + nt*8 + (lane & 3)*2;
            osm[col*132 + px0]         = acc[mi][nt][0];
            osm[(col+1)*132 + px0]     = acc[mi][nt][1];
            osm[col*132 + px0 + 8]     = acc[mi][nt][2];
            osm[(col+1)*132 + px0 + 8] = acc[mi][nt][3];
        }
    __syncthreads();
    for (int i = tid; i < 128*32; i += 256) {
        int co = i >> 5, p4 = (i & 31)*4;
        float4 v = *reinterpret_cast<const float4*>(osm + co*132 + p4);
        float b = bias_s[co];
        v.x += b; v.y += b; v.z += b; v.w += b;
        int cog = Nt*128 + co;
        *reinterpret_cast<float4*>(out + ((size_t)(n*256 + cog))*1024 + OH0*32 + p4) = v;
    }
}

// ---------------- dec1 via mma.sync bf16 split, depth-2, fused BN partials (R13 config) ----------------
__global__ void __launch_bounds__(256, 1) dec1_mma_kernel(
        const __nv_bfloat16* __restrict__ inhi, const __nv_bfloat16* __restrict__ inlo,
        const __nv_bfloat16* __restrict__ whi, const __nv_bfloat16* __restrict__ wlo,
        const float* __restrict__ bias, float* __restrict__ out,
        float* __restrict__ psum, float* __restrict__ psq)
{
    extern __shared__ char dsm[];
    __shared__ float bias_s[128];
    __shared__ float sred[256], qred[256];
    const int NKC[4]  = {4, 8, 8, 16};
    const int KOFS[4] = {0, 256, 768, 1280};
    const int DYT[4][4] = {{0,0,0,0},{0,0,0,0},{1,0,0,0},{1,1,0,0}};
    const int DXT[4][4] = {{0,0,0,0},{1,0,0,0},{0,0,0,0},{1,0,1,0}};

    int mt = blockIdx.x, cls = blockIdx.y, n = blockIdx.z;
    int ph = cls >> 1, pw = cls & 1;
    int Y0 = mt * 4;
    int tid = threadIdx.x, wid = tid >> 5, lane = tid & 31;
    int mrow = (wid >> 1) * 32;
    int ncol = (wid & 1) * 64;

    uint32_t base0 = ((uint32_t)__cvta_generic_to_shared(dsm) + 1023u) & ~1023u;
    for (int i = tid; i < 128; i += 256) bias_s[i] = bias[i];

    int kbase = KOFS[cls];
    int nk = NKC[cls];

    auto fill = [&](int kc, int buf) {
        int t = kc >> 2, ci0 = (kc & 3) << 6;
        int dy = DYT[cls][t], dx = DXT[cls][t];
        uint32_t Ah = base0 + buf*MM_STAGE;
        uint32_t Al = Ah + MM_SPLIT;
        uint32_t Bh = Al + MM_SPLIT;
        uint32_t Bl = Bh + MM_SPLIT;
        for (int i = tid; i < 1024; i += 256) {
            int px = i >> 3, c16 = i & 7;
            int y = Y0 + (px >> 5), x = px & 31;
            int iy = y + dy, ix = x + dx;
            bool ok = (iy < 32) && (ix < 32);
            long off = ((long)(n*32 + (ok ? iy : 0))*32 + (ok ? ix : 0))*256 + ci0 + c16*8;
            uint32_t d = SWZ(px*128 + c16*16);
            cp16z(Ah + d, inhi + off, ok);
            cp16z(Al + d, inlo + off, ok);
        }
        for (int i = tid; i < 1024; i += 256) {
            int co = i >> 3, c16 = i & 7;
            long off = (long)co*2304 + kbase + t*256 + ci0 + c16*8;
            uint32_t d = SWZ(co*128 + c16*16);
            cp16(Bh + d, whi + off);
            cp16(Bl + d, wlo + off);
        }
    };

    float acc[2][8][4];
#pragma unroll
    for (int a = 0; a < 2; a++)
#pragma unroll
        for (int b = 0; b < 8; b++)
#pragma unroll
            for (int c = 0; c < 4; c++) acc[a][b][c] = 0.f;

    fill(0, 0); CP_COMMIT();
    for (int s = 0; s < nk; s++) {
        if (s < nk-1) { fill(s+1, (s+1)&1); CP_COMMIT(); CP_WAIT(1); }
        else          { CP_WAIT(0); }
        __syncthreads();
        uint32_t Ah = base0 + (s&1)*MM_STAGE;
        uint32_t Al = Ah + MM_SPLIT;
        uint32_t Bh = Al + MM_SPLIT;
        uint32_t Bl = Bh + MM_SPLIT;
#pragma unroll
        for (int ks = 0; ks < 4; ks++) {
            uint32_t ah[2][4], al[2][4], bh[4][4], bl[4][4];
#pragma unroll
            for (int mi = 0; mi < 2; mi++) {
                int row = mrow + mi*16 + (lane & 15);
                uint32_t ao = SWZ(row*128 + ks*32 + (lane >> 4)*16);
                ldsm4(ah[mi], Ah + ao);
                ldsm4(al[mi], Al + ao);
            }
#pragma unroll
            for (int nb = 0; nb < 4; nb++) {
                int g = lane >> 3, r = lane & 7;
                int co_l = ncol + nb*16 + ((g >> 1) << 3) + r;
                uint32_t bo = SWZ(co_l*128 + ks*32 + (g & 1)*16);
                ldsm4(bh[nb], Bh + bo);
                ldsm4(bl[nb], Bl + bo);
            }
#pragma unroll
            for (int mi = 0; mi < 2; mi++)
#pragma unroll
                for (int nt = 0; nt < 8; nt++) {
                    const uint32_t* pbh = &bh[nt >> 1][(nt & 1)*2];
                    const uint32_t* pbl = &bl[nt >> 1][(nt & 1)*2];
                    mma16816(acc[mi][nt], ah[mi], pbh);
                    mma16816(acc[mi][nt], ah[mi], pbl);
                    mma16816(acc[mi][nt], al[mi], pbh);
                }
        }
        __syncthreads();
    }

    float* osm = reinterpret_cast<float*>(dsm);   // stride 133 (conflict-free stats sweep)
#pragma unroll
    for (int mi = 0; mi < 2; mi++)
#pragma unroll
        for (int nt = 0; nt < 8; nt++) {
            int px0 = mrow + mi*16 + (lane >> 2);
            int col = ncol + nt*8 + (lane & 3)*2;
            osm[col*133 + px0]         = acc[mi][nt][0];
            osm[(col+1)*133 + px0]     = acc[mi][nt][1];
            osm[col*133 + px0 + 8]     = acc[mi][nt][2];
            osm[(col+1)*133 + px0 + 8] = acc[mi][nt][3];
        }
    __syncthreads();
    for (int i = tid; i < 128*128; i += 256) {
        int co = i >> 7, p = i & 127;
        int y = Y0 + (p >> 5), x = p & 31;
        int oh = 2*y + ph, ow = 2*x + pw;
        out[((size_t)(n*128 + co)*64 + oh)*64 + ow] = osm[co*133 + p] + bias_s[co];
    }
    {
        int co = tid & 127, half = tid >> 7;
        float s = 0.f, sq = 0.f;
        const float* op = osm + co*133 + half*64;
        float b = bias_s[co];
#pragma unroll 8
        for (int j = 0; j < 64; j++) {
            float v = op[j] + b;
            s += v; sq += v*v;
        }
        sred[tid] = s; qred[tid] = sq;
        __syncthreads();
        if (tid < 128) {
            int blk = blockIdx.x + 8*blockIdx.y + 32*blockIdx.z;
            psum[tid*2048 + blk] = sred[tid] + sred[tid + 128];
            psq[tid*2048 + blk]  = qred[tid] + qred[tid + 128];
        }
    }
}

// ---------------- pre 1x1: 256->64, f32x2 (split halves) ----------------
__global__ void pre_kernel(const float* __restrict__ in, const float* __restrict__ w,
                           const float* __restrict__ bias, float* __restrict__ out)
{
    __shared__ float w_t[256*32];
    int n = blockIdx.z, coH = blockIdx.y;
    int s = blockIdx.x * 256 + threadIdx.x;
    for (int i = threadIdx.x; i < 256*32; i += 256) {
        int ci = i >> 5, co = i & 31;
        w_t[i] = w[(size_t)(coH*32 + co)*256 + ci];
    }
    __syncthreads();
    u64 acc[16];
#pragma unroll
    for (int k = 0; k < 16; k++) acc[k] = 0ull;
    const float* ip = in + (size_t)n*256*1024 + s;
#pragma unroll 4
    for (int ci = 0; ci < 256; ci++) {
        float v = ip[(size_t)ci*1024];
        u64 pv = pack2(v, v);
        const ulonglong2* wp = reinterpret_cast<const ulonglong2*>(w_t + ci*32);
#pragma unroll
        for (int k = 0; k < 8; k++) {
            ulonglong2 ww = wp[k];
            acc[2*k]   = fma2(ww.x, pv, acc[2*k]);
            acc[2*k+1] = fma2(ww.y, pv, acc[2*k+1]);
        }
    }
    float* op = out + (size_t)n*64*1024 + (size_t)coH*32*1024 + s;
#pragma unroll
    for (int k = 0; k < 16; k++) {
        float2 v = unpack2(acc[k]);
        op[(size_t)(2*k  )*1024] = v.x + bias[coH*32 + 2*k];
        op[(size_t)(2*k+1)*1024] = v.y + bias[coH*32 + 2*k+1];
    }
}

// ---------------- VQ: 2 positions per thread ----------------
__global__ void vq_kernel(const float* __restrict__ z, const float* __restrict__ cb,
                          float* __restrict__ idx_out, float* __restrict__ losspart)
{
    extern __shared__ float sm[];
    float* cb_s = sm;
    float* csq  = sm + NCODE*VQ_DIM;
    int tid = threadIdx.x;
    for (int i = tid; i < NCODE*VQ_DIM; i += 256) cb_s[i] = cb[i];
    __syncthreads();
    for (int k = tid; k < NCODE; k += 256) {
        float s = 0.f;
#pragma unroll
        for (int d = 0; d < VQ_DIM; d++) { float c = cb_s[k*VQ_DIM + d]; s += c*c; }
        csq[k] = s;
    }
    __syncthreads();

    int s0 = blockIdx.x * 512 + tid;
    int s1 = s0 + 256;
    int bA = s0 >> 10, hwA = s0 & 1023;
    int bB = s1 >> 10, hwB = s1 & 1023;
    const float* zpA = z + (size_t)bA*64*1024 + hwA;
    const float* zpB = z + (size_t)bB*64*1024 + hwB;
    u64 zA[32], zB[32];
    float zsqA = 0.f, zsqB = 0.f;
#pragma unroll
    for (int u = 0; u < 32; u++) {
        float a0 = zpA[(size_t)(2*u)*1024], a1 = zpA[(size_t)(2*u+1)*1024];
        float b0 = zpB[(size_t)(2*u)*1024], b1 = zpB[(size_t)(2*u+1)*1024];
        zsqA += a0*a0 + a1*a1;
        zsqB += b0*b0 + b1*b1;
        zA[u] = pack2(a0, a1);
        zB[u] = pack2(b0, b1);
    }

    float bestA = 3.4e38f, bestB = 3.4e38f;
    int idxA = 0, idxB = 0;
    for (int k = 0; k < NCODE; k++) {
        const ulonglong2* cp2 = reinterpret_cast<const ulonglong2*>(cb_s + k*VQ_DIM);
        u64 dA0 = 0ull, dA1 = 0ull, dB0 = 0ull, dB1 = 0ull;
#pragma unroll
        for (int u = 0; u < 16; u++) {
            ulonglong2 c2 = cp2[u];
            dA0 = fma2(c2.x, zA[2*u],   dA0);
            dA1 = fma2(c2.y, zA[2*u+1], dA1);
            dB0 = fma2(c2.x, zB[2*u],   dB0);
            dB1 = fma2(c2.y, zB[2*u+1], dB1);
        }
        float2 da = unpack2(add2(dA0, dA1));
        float2 db = unpack2(add2(dB0, dB1));
        float cq = csq[k];
        float distA = zsqA - 2.f*(da.x + da.y) + cq;
        float distB = zsqB - 2.f*(db.x + db.y) + cq;
        if (distA < bestA) { bestA = distA; idxA = k; }
        if (distB < bestB) { bestB = distB; idxB = k; }
    }

    float lsum = 0.f;
#pragma unroll
    for (int u = 0; u < 32; u++) {
        float2 za = unpack2(zA[u]);
        float2 zb = unpack2(zB[u]);
        float ca0 = cb_s[idxA*VQ_DIM + 2*u], ca1 = cb_s[idxA*VQ_DIM + 2*u+1];
        float cb0 = cb_s[idxB*VQ_DIM + 2*u], cb1 = cb_s[idxB*VQ_DIM + 2*u+1];
        float dA0 = za.x - ca0, dA1 = za.y - ca1;
        float dB0 = zb.x - cb0, dB1 = zb.y - cb1;
        lsum += dA0*dA0 + dA1*dA1 + dB0*dB0 + dB1*dB1;
    }
    idx_out[s0] = (float)idxA;
    idx_out[s1] = (float)idxB;

    __shared__ float red[256];
    red[tid] = lsum; __syncthreads();
    for (int o = 128; o > 0; o >>= 1) {
        if (tid < o) red[tid] += red[tid + o];
        __syncthreads();
    }
    if (tid == 0) losspart[blockIdx.x] = red[0];
}

__global__ void loss_finalize_kernel(const float* __restrict__ losspart,
                                     float* __restrict__ out_losses)
{
    __shared__ float red[256];
    red[threadIdx.x] = (threadIdx.x < 128) ? losspart[threadIdx.x] : 0.f;
    __syncthreads();
    for (int o = 128; o > 0; o >>= 1) {
        if (threadIdx.x < o) red[threadIdx.x] += red[threadIdx.x + o];
        __syncthreads();
    }
    if (threadIdx.x == 0) {
        float m = red[0] / (65536.f * 64.f);
        out_losses[0] = m;
        out_losses[1] = m;
    }
}

// ---------------- dec2 quad-centric, ci-split x4, vectorized fill ----------------
__global__ void dec2_kernel(const float* __restrict__ in, const float* __restrict__ w,
                            const float* __restrict__ bias, const float* __restrict__ scale,
                            const float* __restrict__ shift, float* __restrict__ out)
{
    extern __shared__ float sm[];
    float* w_s  = sm;
    float* in_s = sm + 3456;
    float* sc_s = sm + 17280;
    float* sh_s = sm + 17408;
    float* red  = sm + 17536;
    int n = blockIdx.y; int tile = blockIdx.x;
    int OH0 = (tile >> 3) * 16, OW0 = (tile & 7) * 16;
    int IH0 = OH0 >> 1, IW0 = OW0 >> 1;
    int tid = threadIdx.x;
    for (int i = tid; i < 3456; i += 256) w_s[i] = w[i];
    for (int i = tid; i < 128; i += 256) { sc_s[i] = scale[i]; sh_s[i] = shift[i]; }
    __syncthreads();
    // vectorized fill: unit = (ci, rr); 2x float4 + 1 bounded scalar per row
    for (int u = tid; u < 128*9; u += 256) {
        int ci = u / 9, rr = u - ci*9;
        int ih = IH0 + rr;
        float* dst = in_s + ci*108 + rr*12;
        float s = sc_s[ci], t = sh_s[ci];
        if (ih < 64) {
            const float* src = in + ((size_t)(n*128 + ci)*64 + ih)*64 + IW0;
            float4 a = *reinterpret_cast<const float4*>(src);
            float4 b = *reinterpret_cast<const float4*>(src + 4);
            float c8 = (IW0 + 8 < 64) ? src[8] : 0.f;
            dst[0] = fmaxf(fmaf(a.x, s, t), 0.f);
            dst[1] = fmaxf(fmaf(a.y, s, t), 0.f);
            dst[2] = fmaxf(fmaf(a.z, s, t), 0.f);
            dst[3] = fmaxf(fmaf(a.w, s, t), 0.f);
            dst[4] = fmaxf(fmaf(b.x, s, t), 0.f);
            dst[5] = fmaxf(fmaf(b.y, s, t), 0.f);
            dst[6] = fmaxf(fmaf(b.z, s, t), 0.f);
            dst[7] = fmaxf(fmaf(b.w, s, t), 0.f);
            dst[8] = (IW0 + 8 < 64) ? fmaxf(fmaf(c8, s, t), 0.f) : 0.f;
        } else {
#pragma unroll
            for (int c = 0; c < 9; c++) dst[c] = 0.f;
        }
    }
    __syncthreads();

    int q = tid & 63, qy = q >> 3, qx = q & 7;
    int cisub = tid >> 6;
    float acc[4][3];
#pragma unroll
    for (int p = 0; p < 4; p++)
#pragma unroll
        for (int co = 0; co < 3; co++) acc[p][co] = 0.f;

    int ci0 = cisub * 32;
#pragma unroll 4
    for (int ci = ci0; ci < ci0 + 32; ci++) {
        const float* base = in_s + ci*108 + qy*12 + qx;
        float v00 = base[0], v01 = base[1], v10 = base[12], v11 = base[13];
        const float* wp = w_s + ci*27;
#pragma unroll
        for (int co = 0; co < 3; co++) {
            const float* wc = wp + co*9;
            acc[0][co] += wc[4]*v00;
            acc[1][co] += wc[3]*v01 + wc[5]*v00;
            acc[2][co] += wc[1]*v10 + wc[7]*v00;
            acc[3][co] += wc[0]*v11 + wc[2]*v10 + wc[6]*v01 + wc[8]*v00;
        }
    }
#pragma unroll
    for (int p = 0; p < 4; p++)
#pragma unroll
        for (int co = 0; co < 3; co++)
            red[(p*3 + co)*256 + tid] = acc[p][co];
    __syncthreads();
    if (tid < 64) {
#pragma unroll
        for (int p = 0; p < 4; p++) {
            int ph = p >> 1, pw = p & 1;
            int oh = OH0 + 2*qy + ph, ow = OW0 + 2*qx + pw;
#pragma unroll
            for (int co = 0; co < 3; co++) {
                int j = p*3 + co;
                float s = red[j*256 + tid] + red[j*256 + tid + 64]
                        + red[j*256 + tid + 128] + red[j*256 + tid + 192];
                out[((size_t)(n*3 + co)*128 + oh)*128 + ow] = tanhf(s + bias[co]);
            }
        }
    }
}

// ---------------- host launch ----------------
static float* sym_addr(const void* sym)
{
    void* p = nullptr;
    cudaGetSymbolAddress(&p, sym);
    return (float*)p;
}

extern "C" void kernel_launch(void* const* d_in, const int* in_sizes, int n_in,
                              void* d_out, int out_size)
{
    const float* x       = (const float*)d_in[0];
    const float* enc1_w  = (const float*)d_in[1];
    const float* enc1_b  = (const float*)d_in[2];
    const float* bn1_g   = (const float*)d_in[3];
    const float* bn1_b   = (const float*)d_in[4];
    const float* enc2_w  = (const float*)d_in[5];
    const float* enc2_b  = (const float*)d_in[6];
    const float* pre_w   = (const float*)d_in[7];
    const float* pre_b   = (const float*)d_in[8];
    const float* codebook= (const float*)d_in[9];
    const float* post_w  = (const float*)d_in[10];
    const float* post_b  = (const float*)d_in[11];
    const float* dec1_w  = (const float*)d_in[12];
    const float* dec1_b  = (const float*)d_in[13];
    const float* dbn1_g  = (const float*)d_in[14];
    const float* dbn1_b  = (const float*)d_in[15];
    const float* dec2_w  = (const float*)d_in[16];
    const float* dec2_b  = (const float*)d_in[17];

    float* out = (float*)d_out;
    float* out_losses = out + RECON_ELEMS;
    float* out_idx    = out + RECON_ELEMS + 2;

    float* h1  = sym_addr(g_h1);
    __nv_bfloat16* h1hi; { void* p; cudaGetSymbolAddress(&p, g_h1hi); h1hi = (__nv_bfloat16*)p; }
    __nv_bfloat16* h1lo; { void* p; cudaGetSymbolAddress(&p, g_h1lo); h1lo = (__nv_bfloat16*)p; }
    __nv_bfloat16* w2chi; { void* p; cudaGetSymbolAddress(&p, g_w2chi); w2chi = (__nv_bfloat16*)p; }
    __nv_bfloat16* w2clo; { void* p; cudaGetSymbolAddress(&p, g_w2clo); w2clo = (__nv_bfloat16*)p; }
    __nv_bfloat16* wd1hi; { void* p; cudaGetSymbolAddress(&p, g_wd1hi); wd1hi = (__nv_bfloat16*)p; }
    __nv_bfloat16* wd1lo; { void* p; cudaGetSymbolAddress(&p, g_wd1lo); wd1lo = (__nv_bfloat16*)p; }
    __nv_bfloat16* dhi; { void* p; cudaGetSymbolAddress(&p, g_dhi); dhi = (__nv_bfloat16*)p; }
    __nv_bfloat16* dlo; { void* p; cudaGetSymbolAddress(&p, g_dlo); dlo = (__nv_bfloat16*)p; }
    __nv_bfloat16* tabhi; { void* p; cudaGetSymbolAddress(&p, g_tabhi); tabhi = (__nv_bfloat16*)p; }
    __nv_bfloat16* tablo; { void* p; cudaGetSymbolAddress(&p, g_tablo); tablo = (__nv_bfloat16*)p; }
    float* h2  = sym_addr(g_h2);
    float* z   = sym_addr(g_z);
    float* d1  = sym_addr(g_d1);
    float* psum = sym_addr(g_psum);
    float* psq  = sym_addr(g_psq);
    float* sc   = sym_addr(g_scale);
    float* sh   = sym_addr(g_shift);
    float* lp   = sym_addr(g_losspart);

    const unsigned MM_SMEM = 2*MM_STAGE + 1024;   // 132096 -> 1 CTA/SM
    cudaFuncSetAttribute(conv2_mma_kernel, cudaFuncAttributeMaxDynamicSharedMemorySize, MM_SMEM);
    cudaFuncSetAttribute(dec1_mma_kernel,  cudaFuncAttributeMaxDynamicSharedMemorySize, MM_SMEM);
    cudaFuncSetAttribute(vq_kernel,   cudaFuncAttributeMaxDynamicSharedMemorySize, 133120);
    cudaFuncSetAttribute(dec2_kernel, cudaFuncAttributeMaxDynamicSharedMemorySize, 84480);

    const float inv_cnt = 1.f / 262144.f;

    conv1_kernel<<<dim3(4,4,64), 256>>>(x, enc1_w, enc1_b, h1);
    bn_stats_nhwc<<<1024, 256>>>(h1, psum, psq, 1024);
    bn_finalize_par<<<128, 256>>>(psum, psq, bn1_g, bn1_b, sc, sh, 1024, inv_cnt);
    bnrelu_split_kernel<<<32768, 256>>>(h1, h1hi, h1lo, sc, sh);
    wtrans_conv2_bf16<<<1152, 256>>>(enc2_w, w2chi, w2clo);
    conv2_mma_kernel<<<dim3(8,2,64), 256, MM_SMEM>>>(h1hi, h1lo, w2chi, w2clo, enc2_b, h2);
    wtrans_dec1_bf16<<<1152, 256>>>(dec1_w, wd1hi, wd1lo);
    table_kernel<<<512, 256>>>(post_w, post_b, codebook, tabhi, tablo);
    pre_kernel<<<dim3(4,2,64), 256>>>(h2, pre_w, pre_b, z);

    vq_kernel<<<128, 256, 133120>>>(z, codebook, out_idx, lp);
    loss_finalize_kernel<<<1,256>>>(lp, out_losses);
    gather_d<<<2048, 256>>>(out_idx, (const uint4*)tabhi, (const uint4*)tablo,
                            (uint4*)dhi, (uint4*)dlo);

    dec1_mma_kernel<<<dim3(8,4,64), 256, MM_SMEM>>>(dhi, dlo, wd1hi, wd1lo, dec1_b, d1, psum, psq);
    bn_finalize_par<<<128, 256>>>(psum, psq, dbn1_g, dbn1_b, sc, sh, 2048, inv_cnt);
    dec2_kernel<<<dim3(64,64), 256, 84480>>>(d1, dec2_w, dec2_b, sc, sh, out);

    (void)in_sizes; (void)n_in; (void)out_size;
}